// round 12
// baseline (speedup 1.0000x reference)
#include <cuda_runtime.h>
#include <cuda_fp16.h>
#include <cstdint>

#define KC    64            // number of selected columns
#define DCOL  1024          // columns of x
#define NTRI  2016          // upper-triangular terms
#define NEVEN 1024          // even-i triangle entries (packed first)
#define NM3   512
#define NM4   512
#define NM5   512
#define TPB   128
#define QROWS 64            // rows per quad CTA (2 threads/row)
#define NQBLK 512           // 512 * 64 = 32768 rows
#define TROWS 128           // rows per mono tile
#define NTILES 256
#define NROWS 32768
#define NSPLIT 8            // mono CTAs per tile (term eighths)
#define NMQ   (NM3/NSPLIT)  // 64 terms of each table per mono-CTA

// -------- persistent scratch (no allocations allowed) --------
__device__ uint2    g_rec3[NM3];     // x: i0|i1<<8|i2<<16, y: c bits
__device__ uint2    g_rec4[NM4];     // x: i0..i3 packed bytes, y: c bits
__device__ uint4    g_rec5[NM5];     // x: i0..i3 bytes, y: i4, z: c bits, w: pad
__device__ __half   g_xs[NTILES * KC * TROWS];  // 4 MB fp16 gathered tiles [tile][col][row]

// half the quadratic form: triangle rows with i ≡ H (mod 2),
// coefficients streamed contiguously from the parity-packed array.
template<int H>
__device__ __forceinline__ float quad_half(const float* __restrict__ s_tri,
                                           const float (&xv)[KC])
{
    const float4* tri4 = (const float4*)s_tri;
    float4 tb = make_float4(0.f, 0.f, 0.f, 0.f);
    float acc = 0.f;
    int p = H ? NEVEN : 0;
    #pragma unroll
    for (int i = H; i < KC - 1; i += 2) {
        float s = 0.f;
        #pragma unroll
        for (int j = i + 1; j < KC; ++j) {
            if ((p & 3) == 0) tb = tri4[p >> 2];
            float bv = ((p & 3) == 0) ? tb.x :
                       ((p & 3) == 1) ? tb.y :
                       ((p & 3) == 2) ? tb.z : tb.w;
            s = fmaf(bv, xv[j], s);
            ++p;
        }
        acc = fmaf(s, xv[i], acc);
    }
    return acc;
}

// -------- kernel 1: gather + linear + quadratic (2 threads/row) -------------
// block 0 additionally packs the monomial record tables (hidden in slack).
__global__ __launch_bounds__(TPB)
void quad_kernel(const float* __restrict__ x, float* __restrict__ out,
                 const float* __restrict__ b,
                 const int*   __restrict__ S,
                 const float* __restrict__ a,
                 const int*   __restrict__ idx3, const float* __restrict__ c3,
                 const int*   __restrict__ idx4, const float* __restrict__ c4,
                 const int*   __restrict__ idx5, const float* __restrict__ c5)
{
    const int tid = threadIdx.x;

    __shared__ float    s_tri[NTRI];       // 8064 B, parity-packed triu(b,1)
    __shared__ float    s_a[KC];
    __shared__ unsigned s_xi[KC];
    __shared__ __half   s_xh[KC][QROWS];   // 8 KB fp16 exchange tile
    __shared__ float    s_q[2][QROWS];     // per-row partials

    // build parity-packed triangle directly from b:
    // even i=2m: base = m*(64-m);  odd i=2m+1: base = NEVEN + m*(63-m)
    {
        const int half = tid >> 6;        // row parity handled per iteration
        const int lane = tid & 63;
        #pragma unroll 1
        for (int i = half; i < 63; i += 2) {
            int cnt = 63 - i;
            int m   = i >> 1;
            int base = ((i & 1) == 0) ? (m * (64 - m)) : (NEVEN + m * (63 - m));
            if (lane < cnt)
                s_tri[base + lane] = b[i * 64 + (i + 1 + lane)];
        }
        if (tid < KC) { s_a[tid] = a[tid]; s_xi[tid] = (unsigned)S[tid]; }
    }

    // block 0: pack monomial records for mono_kernel (kernel-boundary ordered)
    if (blockIdx.x == 0) {
        for (int t = tid; t < NM3; t += TPB) {
            unsigned p = (unsigned)idx3[t*3+0] | ((unsigned)idx3[t*3+1] << 8)
                       | ((unsigned)idx3[t*3+2] << 16);
            uint2 r; r.x = p; r.y = __float_as_uint(c3[t]);
            g_rec3[t] = r;
        }
        for (int t = tid; t < NM4; t += TPB) {
            unsigned p = (unsigned)idx4[t*4+0] | ((unsigned)idx4[t*4+1] << 8)
                       | ((unsigned)idx4[t*4+2] << 16) | ((unsigned)idx4[t*4+3] << 24);
            uint2 r; r.x = p; r.y = __float_as_uint(c4[t]);
            g_rec4[t] = r;
        }
        for (int t = tid; t < NM5; t += TPB) {
            unsigned p = (unsigned)idx5[t*5+0] | ((unsigned)idx5[t*5+1] << 8)
                       | ((unsigned)idx5[t*5+2] << 16) | ((unsigned)idx5[t*5+3] << 24);
            uint4 r; r.x = p; r.y = (unsigned)idx5[t*5+4];
            r.z = __float_as_uint(c5[t]); r.w = 0u;
            g_rec5[t] = r;
        }
    }
    __syncthreads();

    const int lrow = tid & (QROWS - 1);   // row within CTA, 0..63
    const int h    = tid >> 6;            // column half 0/1 (warp-uniform)
    const long long grow = (long long)blockIdx.x * QROWS + lrow;
    const float* xr = x + grow * DCOL;

    float xv[KC];

    // gather own 32 columns (fp32, kept in regs); publish fp16 + spill tile
    {
        const int k0 = 32 * h;
        #pragma unroll
        for (int k = 0; k < 32; ++k) xv[k0 + k] = __ldg(xr + s_xi[k0 + k]);

        const int mtile = blockIdx.x >> 1;
        const int mrow  = ((blockIdx.x & 1) << 6) + lrow;  // row in mono tile
        __half* xt = g_xs + (size_t)mtile * (KC * TROWS);
        #pragma unroll
        for (int k = 0; k < 32; ++k) {
            __half hv = __float2half(xv[k0 + k]);
            s_xh[k0 + k][lrow] = hv;
            xt[(k0 + k) * TROWS + mrow] = hv;
        }
    }
    __syncthreads();

    // fetch the other 32 columns from the fp16 exchange tile
    {
        const int k0 = 32 * (1 - h);
        #pragma unroll
        for (int k = 0; k < 32; ++k) xv[k0 + k] = __half2float(s_xh[k0 + k][lrow]);
    }

    // quadratic half (+ linear on h=1)
    {
        float a0;
        if (h == 0) {
            a0 = quad_half<0>(s_tri, xv);
        } else {
            float l = 0.f;
            #pragma unroll
            for (int k = 0; k < KC; ++k) l = fmaf(s_a[k], xv[k], l);
            a0 = l + quad_half<1>(s_tri, xv);
        }
        s_q[h][lrow] = a0;
    }
    __syncthreads();

    if (tid < QROWS)
        out[grow - lrow + tid] = s_q[0][tid] + s_q[1][tid];
}

__device__ __forceinline__ __half2 as_h2(unsigned u) {
    __half2 h;
    *reinterpret_cast<unsigned*>(&h) = u;
    return h;
}

// -------- kernel 2: monomials; 8 CTAs per tile (term eighths) ---------------
__global__ __launch_bounds__(TPB)
void mono_kernel(float* __restrict__ out)
{
    __shared__ __half s_x[KC][TROWS];    // 16 KB, row stride 256B
    __shared__ float  s_redf[4][TROWS];  // 2 KB

    const int tid  = threadIdx.x;
    const int tile = blockIdx.x >> 3;
    const int par  = blockIdx.x & 7;

    // coalesced tile load: 16 KB = 1024 uint4 (L2-resident, just written)
    {
        const uint4* src = (const uint4*)(g_xs + (size_t)tile * (KC * TROWS));
        uint4*       dst = (uint4*)&s_x[0][0];
        #pragma unroll
        for (int i = 0; i < 8; ++i) dst[tid + i * TPB] = __ldg(src + tid + i * TPB);
    }
    __syncthreads();

    // 32 four-row groups x 4 warp slices (conflict-free LDS.64)
    const int g = tid & 31;             // group id: rows 4g..4g+3
    const int q = tid >> 5;             // warp slice 0..3
    const char* xb = (const char*)(&s_x[0][0]) + 8 * g;  // operand offset = idx<<8
    const int base = par * NMQ;         // this CTA's term eighth
    float m0 = 0.f, m1 = 0.f, m2 = 0.f, m3 = 0.f;

    {
        const int lo = base + q * (NMQ / 4), hi = lo + (NMQ / 4);
        #pragma unroll 4
        for (int t3 = lo; t3 < hi; ++t3) {
            uint2 r = __ldg(&g_rec3[t3]);
            unsigned o0 = (r.x << 8) & 0xFF00u;
            unsigned o1 =  r.x       & 0xFF00u;
            unsigned o2 = (r.x >> 8) & 0xFF00u;
            uint2 u0 = *(const uint2*)(xb + o0);
            uint2 u1 = *(const uint2*)(xb + o1);
            uint2 u2 = *(const uint2*)(xb + o2);
            __half2 pa = __hmul2(__hmul2(as_h2(u0.x), as_h2(u1.x)), as_h2(u2.x));
            __half2 pb = __hmul2(__hmul2(as_h2(u0.y), as_h2(u1.y)), as_h2(u2.y));
            float2 fa = __half22float2(pa);
            float2 fb = __half22float2(pb);
            float c = __uint_as_float(r.y);
            m0 = fmaf(c, fa.x, m0);
            m1 = fmaf(c, fa.y, m1);
            m2 = fmaf(c, fb.x, m2);
            m3 = fmaf(c, fb.y, m3);
        }
    }
    {
        const int lo = base + q * (NMQ / 4), hi = lo + (NMQ / 4);
        #pragma unroll 4
        for (int t4 = lo; t4 < hi; ++t4) {
            uint2 r = __ldg(&g_rec4[t4]);
            unsigned o0 = (r.x << 8)  & 0xFF00u;
            unsigned o1 =  r.x        & 0xFF00u;
            unsigned o2 = (r.x >> 8)  & 0xFF00u;
            unsigned o3 = (r.x >> 16) & 0xFF00u;
            uint2 u0 = *(const uint2*)(xb + o0);
            uint2 u1 = *(const uint2*)(xb + o1);
            uint2 u2 = *(const uint2*)(xb + o2);
            uint2 u3 = *(const uint2*)(xb + o3);
            __half2 pa = __hmul2(__hmul2(as_h2(u0.x), as_h2(u1.x)),
                                 __hmul2(as_h2(u2.x), as_h2(u3.x)));
            __half2 pb = __hmul2(__hmul2(as_h2(u0.y), as_h2(u1.y)),
                                 __hmul2(as_h2(u2.y), as_h2(u3.y)));
            float2 fa = __half22float2(pa);
            float2 fb = __half22float2(pb);
            float c = __uint_as_float(r.y);
            m0 = fmaf(c, fa.x, m0);
            m1 = fmaf(c, fa.y, m1);
            m2 = fmaf(c, fb.x, m2);
            m3 = fmaf(c, fb.y, m3);
        }
    }
    {
        const int lo = base + q * (NMQ / 4), hi = lo + (NMQ / 4);
        #pragma unroll 4
        for (int t5 = lo; t5 < hi; ++t5) {
            uint4 r = __ldg(&g_rec5[t5]);
            unsigned o0 = (r.x << 8)  & 0xFF00u;
            unsigned o1 =  r.x        & 0xFF00u;
            unsigned o2 = (r.x >> 8)  & 0xFF00u;
            unsigned o3 = (r.x >> 16) & 0xFF00u;
            unsigned o4 =  r.y << 8;
            uint2 u0 = *(const uint2*)(xb + o0);
            uint2 u1 = *(const uint2*)(xb + o1);
            uint2 u2 = *(const uint2*)(xb + o2);
            uint2 u3 = *(const uint2*)(xb + o3);
            uint2 u4 = *(const uint2*)(xb + o4);
            __half2 pa = __hmul2(__hmul2(__hmul2(as_h2(u0.x), as_h2(u1.x)),
                                         __hmul2(as_h2(u2.x), as_h2(u3.x))),
                                 as_h2(u4.x));
            __half2 pb = __hmul2(__hmul2(__hmul2(as_h2(u0.y), as_h2(u1.y)),
                                         __hmul2(as_h2(u2.y), as_h2(u3.y))),
                                 as_h2(u4.y));
            float2 fa = __half22float2(pa);
            float2 fb = __half22float2(pb);
            float c = __uint_as_float(r.z);
            m0 = fmaf(c, fa.x, m0);
            m1 = fmaf(c, fa.y, m1);
            m2 = fmaf(c, fb.x, m2);
            m3 = fmaf(c, fb.y, m3);
        }
    }

    *(float4*)&s_redf[q][4 * g] = make_float4(m0, m1, m2, m3);
    __syncthreads();

    // one thread per row: combine this CTA's 4 slices, accumulate to out
    {
        float r = s_redf[0][tid] + s_redf[1][tid] + s_redf[2][tid] + s_redf[3][tid];
        atomicAdd(out + (size_t)tile * TROWS + tid, r);
    }
}

// -------- launch --------
extern "C" void kernel_launch(void* const* d_in, const int* in_sizes, int n_in,
                              void* d_out, int out_size)
{
    const float* x    = (const float*)d_in[0];
    const int*   S    = (const int*)  d_in[1];
    const float* a    = (const float*)d_in[2];
    const float* b    = (const float*)d_in[3];
    const int*   idx3 = (const int*)  d_in[4];
    const float* c3   = (const float*)d_in[5];
    const int*   idx4 = (const int*)  d_in[6];
    const float* c4   = (const float*)d_in[7];
    const int*   idx5 = (const int*)  d_in[8];
    const float* c5   = (const float*)d_in[9];
    float* out = (float*)d_out;

    // quad: out = lin+quad (2 threads/row), spills fp16 tiles; block 0 packs records
    quad_kernel<<<NQBLK, TPB>>>(x, out, b, S, a,
                                idx3, c3, idx4, c4, idx5, c5);
    // mono: += monomials (8 term-eighths per tile)
    mono_kernel<<<NTILES * NSPLIT, TPB>>>(out);
}

// round 13
// speedup vs baseline: 1.0372x; 1.0372x over previous
#include <cuda_runtime.h>
#include <cuda_fp16.h>
#include <cstdint>

#define KC    64            // number of selected columns
#define DCOL  1024          // columns of x
#define NTRI  2016          // upper-triangular terms
#define NEVEN 1024          // even-i triangle entries (packed first)
#define NM3   512
#define NM4   512
#define NM5   512
#define TPB   128
#define QROWS 64            // rows per quad CTA (2 threads/row)
#define NQBLK 512           // 512 * 64 = 32768 rows
#define TROWS 128           // rows per mono tile
#define NTILES 256
#define NROWS 32768
#define NSPLIT 8            // mono CTAs per tile (term eighths)
#define NMQ   (NM3/NSPLIT)  // 64 terms of each table per mono-CTA

// -------- persistent scratch (no allocations allowed) --------
__device__ uint2    g_rec3[NM3];     // x: i0|i1<<8|i2<<16, y: c bits
__device__ uint2    g_rec4[NM4];     // x: i0..i3 packed bytes, y: c bits
__device__ uint4    g_rec5[NM5];     // x: i0..i3 bytes, y: i4, z: c bits, w: pad
__device__ __half   g_xs[NTILES * KC * TROWS];  // 4 MB fp16 gathered tiles [tile][col][row]

// parity-packed triangle bases (even rows i=2m first, then odd i=2m+1)
__device__ __forceinline__ int base_e(int m) { return m * (64 - m); }
__device__ __forceinline__ int base_o(int m) { return m * (63 - m); }

// half the quadratic form: triangle rows with i ≡ H (mod 2),
// coefficients streamed contiguously from the parity-packed array.
template<int H>
__device__ __forceinline__ float quad_half(const float* __restrict__ s_tri,
                                           const float (&xv)[KC])
{
    const float4* tri4 = (const float4*)s_tri;
    float4 tb = make_float4(0.f, 0.f, 0.f, 0.f);
    float acc = 0.f;
    int p = H ? NEVEN : 0;
    #pragma unroll
    for (int i = H; i < KC - 1; i += 2) {
        float s = 0.f;
        #pragma unroll
        for (int j = i + 1; j < KC; ++j) {
            if ((p & 3) == 0) tb = tri4[p >> 2];
            float bv = ((p & 3) == 0) ? tb.x :
                       ((p & 3) == 1) ? tb.y :
                       ((p & 3) == 2) ? tb.z : tb.w;
            s = fmaf(bv, xv[j], s);
            ++p;
        }
        acc = fmaf(s, xv[i], acc);
    }
    return acc;
}

// -------- kernel 1: gather + linear + quadratic (2 threads/row) -------------
// block 0 additionally packs the monomial record tables (hidden in slack).
__global__ __launch_bounds__(TPB)
void quad_kernel(const float* __restrict__ x, float* __restrict__ out,
                 const float* __restrict__ b,
                 const int*   __restrict__ S,
                 const float* __restrict__ a,
                 const int*   __restrict__ idx3, const float* __restrict__ c3,
                 const int*   __restrict__ idx4, const float* __restrict__ c4,
                 const int*   __restrict__ idx5, const float* __restrict__ c5)
{
    const int tid = threadIdx.x;

    __shared__ float    s_tri[NTRI];       // 8064 B, parity-packed triu(b,1)
    __shared__ float    s_a[KC];
    __shared__ unsigned s_xi[KC];
    __shared__ __half   s_xh[KC][QROWS];   // 8 KB fp16 exchange tile
    __shared__ float    s_q[2][QROWS];     // per-row partials

    // ---- latency-flat triangle pack: 16 slots/thread, batched LDG then STS --
    {
        int   dsti[16];
        int   srci[16];
        #pragma unroll
        for (int s = 0; s < 16; ++s) {
            int p = tid + s * TPB;          // packed (parity) index
            int i, j;
            if (p < NEVEN) {                 // even rows i = 2m
                int m = (int)(32.0f - sqrtf((float)(1024 - p)));
                if (m < 0) m = 0; if (m > 31) m = 31;
                while (m > 0  && base_e(m)     > p) --m;
                while (m < 31 && base_e(m + 1) <= p) ++m;
                i = 2 * m;  j = i + 1 + (p - base_e(m));
            } else {                         // odd rows i = 2m+1
                int q = p - NEVEN;
                int m = (int)(31.5f - sqrtf(992.25f - (float)q));
                if (m < 0) m = 0; if (m > 30) m = 30;
                while (m > 0  && base_o(m)     > q) --m;
                while (m < 30 && base_o(m + 1) <= q) ++m;
                i = 2 * m + 1;  j = i + 1 + (q - base_o(m));
            }
            dsti[s] = p;
            srci[s] = i * 64 + j;
        }
        float v[16];
        #pragma unroll
        for (int s = 0; s < 16; ++s)
            v[s] = (dsti[s] < NTRI) ? __ldg(b + srci[s]) : 0.f;
        #pragma unroll
        for (int s = 0; s < 16; ++s)
            if (dsti[s] < NTRI) s_tri[dsti[s]] = v[s];

        if (tid < KC) { s_a[tid] = a[tid]; s_xi[tid] = (unsigned)S[tid]; }
    }

    // block 0: pack monomial records for mono_kernel (kernel-boundary ordered)
    if (blockIdx.x == 0) {
        for (int t = tid; t < NM3; t += TPB) {
            unsigned p = (unsigned)idx3[t*3+0] | ((unsigned)idx3[t*3+1] << 8)
                       | ((unsigned)idx3[t*3+2] << 16);
            uint2 r; r.x = p; r.y = __float_as_uint(c3[t]);
            g_rec3[t] = r;
        }
        for (int t = tid; t < NM4; t += TPB) {
            unsigned p = (unsigned)idx4[t*4+0] | ((unsigned)idx4[t*4+1] << 8)
                       | ((unsigned)idx4[t*4+2] << 16) | ((unsigned)idx4[t*4+3] << 24);
            uint2 r; r.x = p; r.y = __float_as_uint(c4[t]);
            g_rec4[t] = r;
        }
        for (int t = tid; t < NM5; t += TPB) {
            unsigned p = (unsigned)idx5[t*5+0] | ((unsigned)idx5[t*5+1] << 8)
                       | ((unsigned)idx5[t*5+2] << 16) | ((unsigned)idx5[t*5+3] << 24);
            uint4 r; r.x = p; r.y = (unsigned)idx5[t*5+4];
            r.z = __float_as_uint(c5[t]); r.w = 0u;
            g_rec5[t] = r;
        }
    }
    __syncthreads();

    const int lrow = tid & (QROWS - 1);   // row within CTA, 0..63
    const int h    = tid >> 6;            // column half 0/1 (warp-uniform)
    const long long grow = (long long)blockIdx.x * QROWS + lrow;
    const float* xr = x + grow * DCOL;

    float xv[KC];

    // gather own 32 columns (fp32, kept in regs); publish fp16 + spill tile
    {
        const int k0 = 32 * h;
        #pragma unroll
        for (int k = 0; k < 32; ++k) xv[k0 + k] = __ldg(xr + s_xi[k0 + k]);

        const int mtile = blockIdx.x >> 1;
        const int mrow  = ((blockIdx.x & 1) << 6) + lrow;  // row in mono tile
        __half* xt = g_xs + (size_t)mtile * (KC * TROWS);
        #pragma unroll
        for (int k = 0; k < 32; ++k) {
            __half hv = __float2half(xv[k0 + k]);
            s_xh[k0 + k][lrow] = hv;
            xt[(k0 + k) * TROWS + mrow] = hv;
        }
    }
    __syncthreads();

    // fetch the other 32 columns from the fp16 exchange tile
    {
        const int k0 = 32 * (1 - h);
        #pragma unroll
        for (int k = 0; k < 32; ++k) xv[k0 + k] = __half2float(s_xh[k0 + k][lrow]);
    }

    // quadratic half (+ linear on h=1)
    {
        float a0;
        if (h == 0) {
            a0 = quad_half<0>(s_tri, xv);
        } else {
            float l = 0.f;
            #pragma unroll
            for (int k = 0; k < KC; ++k) l = fmaf(s_a[k], xv[k], l);
            a0 = l + quad_half<1>(s_tri, xv);
        }
        s_q[h][lrow] = a0;
    }
    __syncthreads();

    if (tid < QROWS)
        out[grow - lrow + tid] = s_q[0][tid] + s_q[1][tid];
}

__device__ __forceinline__ __half2 as_h2(unsigned u) {
    __half2 h;
    *reinterpret_cast<unsigned*>(&h) = u;
    return h;
}

// -------- kernel 2: monomials; 8 CTAs per tile (term eighths) ---------------
__global__ __launch_bounds__(TPB)
void mono_kernel(float* __restrict__ out)
{
    __shared__ __half s_x[KC][TROWS];    // 16 KB, row stride 256B
    __shared__ float  s_redf[4][TROWS];  // 2 KB

    const int tid  = threadIdx.x;
    const int tile = blockIdx.x >> 3;
    const int par  = blockIdx.x & 7;

    // coalesced tile load: 16 KB = 1024 uint4 (L2-resident, just written)
    {
        const uint4* src = (const uint4*)(g_xs + (size_t)tile * (KC * TROWS));
        uint4*       dst = (uint4*)&s_x[0][0];
        #pragma unroll
        for (int i = 0; i < 8; ++i) dst[tid + i * TPB] = __ldg(src + tid + i * TPB);
    }
    __syncthreads();

    // 32 four-row groups x 4 warp slices (conflict-free LDS.64)
    const int g = tid & 31;             // group id: rows 4g..4g+3
    const int q = tid >> 5;             // warp slice 0..3
    const char* xb = (const char*)(&s_x[0][0]) + 8 * g;  // operand offset = idx<<8
    const int base = par * NMQ;         // this CTA's term eighth
    float m0 = 0.f, m1 = 0.f, m2 = 0.f, m3 = 0.f;

    {
        const int lo = base + q * (NMQ / 4), hi = lo + (NMQ / 4);
        #pragma unroll 4
        for (int t3 = lo; t3 < hi; ++t3) {
            uint2 r = __ldg(&g_rec3[t3]);
            unsigned o0 = (r.x << 8) & 0xFF00u;
            unsigned o1 =  r.x       & 0xFF00u;
            unsigned o2 = (r.x >> 8) & 0xFF00u;
            uint2 u0 = *(const uint2*)(xb + o0);
            uint2 u1 = *(const uint2*)(xb + o1);
            uint2 u2 = *(const uint2*)(xb + o2);
            __half2 pa = __hmul2(__hmul2(as_h2(u0.x), as_h2(u1.x)), as_h2(u2.x));
            __half2 pb = __hmul2(__hmul2(as_h2(u0.y), as_h2(u1.y)), as_h2(u2.y));
            float2 fa = __half22float2(pa);
            float2 fb = __half22float2(pb);
            float c = __uint_as_float(r.y);
            m0 = fmaf(c, fa.x, m0);
            m1 = fmaf(c, fa.y, m1);
            m2 = fmaf(c, fb.x, m2);
            m3 = fmaf(c, fb.y, m3);
        }
    }
    {
        const int lo = base + q * (NMQ / 4), hi = lo + (NMQ / 4);
        #pragma unroll 4
        for (int t4 = lo; t4 < hi; ++t4) {
            uint2 r = __ldg(&g_rec4[t4]);
            unsigned o0 = (r.x << 8)  & 0xFF00u;
            unsigned o1 =  r.x        & 0xFF00u;
            unsigned o2 = (r.x >> 8)  & 0xFF00u;
            unsigned o3 = (r.x >> 16) & 0xFF00u;
            uint2 u0 = *(const uint2*)(xb + o0);
            uint2 u1 = *(const uint2*)(xb + o1);
            uint2 u2 = *(const uint2*)(xb + o2);
            uint2 u3 = *(const uint2*)(xb + o3);
            __half2 pa = __hmul2(__hmul2(as_h2(u0.x), as_h2(u1.x)),
                                 __hmul2(as_h2(u2.x), as_h2(u3.x)));
            __half2 pb = __hmul2(__hmul2(as_h2(u0.y), as_h2(u1.y)),
                                 __hmul2(as_h2(u2.y), as_h2(u3.y)));
            float2 fa = __half22float2(pa);
            float2 fb = __half22float2(pb);
            float c = __uint_as_float(r.y);
            m0 = fmaf(c, fa.x, m0);
            m1 = fmaf(c, fa.y, m1);
            m2 = fmaf(c, fb.x, m2);
            m3 = fmaf(c, fb.y, m3);
        }
    }
    {
        const int lo = base + q * (NMQ / 4), hi = lo + (NMQ / 4);
        #pragma unroll 4
        for (int t5 = lo; t5 < hi; ++t5) {
            uint4 r = __ldg(&g_rec5[t5]);
            unsigned o0 = (r.x << 8)  & 0xFF00u;
            unsigned o1 =  r.x        & 0xFF00u;
            unsigned o2 = (r.x >> 8)  & 0xFF00u;
            unsigned o3 = (r.x >> 16) & 0xFF00u;
            unsigned o4 =  r.y << 8;
            uint2 u0 = *(const uint2*)(xb + o0);
            uint2 u1 = *(const uint2*)(xb + o1);
            uint2 u2 = *(const uint2*)(xb + o2);
            uint2 u3 = *(const uint2*)(xb + o3);
            uint2 u4 = *(const uint2*)(xb + o4);
            __half2 pa = __hmul2(__hmul2(__hmul2(as_h2(u0.x), as_h2(u1.x)),
                                         __hmul2(as_h2(u2.x), as_h2(u3.x))),
                                 as_h2(u4.x));
            __half2 pb = __hmul2(__hmul2(__hmul2(as_h2(u0.y), as_h2(u1.y)),
                                         __hmul2(as_h2(u2.y), as_h2(u3.y))),
                                 as_h2(u4.y));
            float2 fa = __half22float2(pa);
            float2 fb = __half22float2(pb);
            float c = __uint_as_float(r.z);
            m0 = fmaf(c, fa.x, m0);
            m1 = fmaf(c, fa.y, m1);
            m2 = fmaf(c, fb.x, m2);
            m3 = fmaf(c, fb.y, m3);
        }
    }

    *(float4*)&s_redf[q][4 * g] = make_float4(m0, m1, m2, m3);
    __syncthreads();

    // one thread per row: combine this CTA's 4 slices, accumulate to out
    {
        float r = s_redf[0][tid] + s_redf[1][tid] + s_redf[2][tid] + s_redf[3][tid];
        atomicAdd(out + (size_t)tile * TROWS + tid, r);
    }
}

// -------- launch --------
extern "C" void kernel_launch(void* const* d_in, const int* in_sizes, int n_in,
                              void* d_out, int out_size)
{
    const float* x    = (const float*)d_in[0];
    const int*   S    = (const int*)  d_in[1];
    const float* a    = (const float*)d_in[2];
    const float* b    = (const float*)d_in[3];
    const int*   idx3 = (const int*)  d_in[4];
    const float* c3   = (const float*)d_in[5];
    const int*   idx4 = (const int*)  d_in[6];
    const float* c4   = (const float*)d_in[7];
    const int*   idx5 = (const int*)  d_in[8];
    const float* c5   = (const float*)d_in[9];
    float* out = (float*)d_out;

    // quad: out = lin+quad (2 threads/row), spills fp16 tiles; block 0 packs records
    quad_kernel<<<NQBLK, TPB>>>(x, out, b, S, a,
                                idx3, c3, idx4, c4, idx5, c5);
    // mono: += monomials (8 term-eighths per tile)
    mono_kernel<<<NTILES * NSPLIT, TPB>>>(out);
}